// round 6
// baseline (speedup 1.0000x reference)
#include <cuda_runtime.h>
#include <cuda_bf16.h>
#include <cstdint>

// Problem constants (fixed shapes per reference)
#define Bn   8
#define Nn   1024
#define Fin  128
#define Cc   128
#define Ef   64
#define Hh   4
#define NEG  0.2f
#define ROWS (Bn * Nn)          // 8192
#define ICHUNK 16               // i-rows per block in main kernel

// Scratch (device globals — no allocation allowed).
// g_cnt starts BSS-zero and is re-zeroed (sparsely) at the tail of every
// launch sequence, so each run begins with a zero count matrix.
__device__ float4 g_S [ROWS];               // s  = src @ (W_lin@a_src)
__device__ float4 g_D [ROWS];               // d  = src @ (W_lin@a_dst)
__device__ float4 g_P [ROWS];               // p  = src @ (W_edge@a_edge)
__device__ float4 g_ES [ROWS];              // exp(s)
__device__ float4 g_ES2[ROWS];              // exp(0.2 s)
__device__ float4 g_ED [ROWS];              // exp(d)
__device__ float4 g_ED2[ROWS];              // exp(0.2 d)
__device__ int    g_cnt[Nn * Nn];           // edge multiplicity matrix

// ---------------------------------------------------------------------------
// Kernel 1: fused prep.
//   phase 0: scatter edge multiplicities (atomics, cnt pre-zeroed)
//   phase 1: fold weights M = [WL@as | WL@ad | WE@ae] into smem (per block)
//   phase 2: warp-per-row projections + exponentials
// ---------------------------------------------------------------------------
__global__ __launch_bounds__(256) void prep_kernel(
        const float* __restrict__ src,
        const int*   __restrict__ edge_index, int E,
        const float* __restrict__ W_lin,
        const float* __restrict__ a_src,
        const float* __restrict__ a_dst,
        const float* __restrict__ W_edge,
        const float* __restrict__ a_edge) {
    // ---- phase 0: scatter (independent of the rest; completes by kernel end)
    {
        int t = blockIdx.x * blockDim.x + threadIdx.x;
        int nt = gridDim.x * blockDim.x;
        for (int e = t; e < E; e += nt) {
            int i = edge_index[e];
            int j = edge_index[E + e];
            atomicAdd(&g_cnt[i * Nn + j], 1);
        }
    }

    // ---- phase 1: M in smem (redundant per block; 1536 dot products)
    __shared__ float sM[Fin * 12];
    for (int idx = threadIdx.x; idx < Fin * 12; idx += 256) {
        const int f = idx / 12;
        const int k = idx % 12;
        float acc = 0.0f;
        if (k < 8) {
            const float* av = (k < 4) ? a_src : a_dst;
            const int h = k & 3;
            #pragma unroll 4
            for (int c = 0; c < Cc; c++) acc += W_lin[f * Cc + c] * av[c * Hh + h];
        } else {
            const int h = k - 8;
            #pragma unroll 4
            for (int d = 0; d < Ef; d++) acc += W_edge[f * Ef + d] * a_edge[d * Hh + h];
        }
        sM[idx] = acc;
    }
    __syncthreads();

    // ---- phase 2: rows (warp per row)
    const int gwarp  = (blockIdx.x * blockDim.x + threadIdx.x) >> 5;
    const int lane   = threadIdx.x & 31;
    const int nwarps = (gridDim.x * blockDim.x) >> 5;

    for (int r = gwarp; r < ROWS; r += nwarps) {
        const float4 sv = reinterpret_cast<const float4*>(src + (size_t)r * Fin)[lane];
        float acc[12];
        #pragma unroll
        for (int h = 0; h < 12; h++) acc[h] = 0.0f;

        float vals[4] = {sv.x, sv.y, sv.z, sv.w};
        #pragma unroll
        for (int k = 0; k < 4; k++) {
            const int f = lane * 4 + k;
            const float x = vals[k];
            #pragma unroll
            for (int h = 0; h < 12; h++) acc[h] += x * sM[f * 12 + h];
        }
        #pragma unroll
        for (int o = 16; o > 0; o >>= 1) {
            #pragma unroll
            for (int h = 0; h < 12; h++)
                acc[h] += __shfl_xor_sync(0xffffffffu, acc[h], o);
        }
        if (lane == 0) {
            float4 s = make_float4(acc[0], acc[1], acc[2],  acc[3]);
            float4 d = make_float4(acc[4], acc[5], acc[6],  acc[7]);
            float4 p = make_float4(acc[8], acc[9], acc[10], acc[11]);
            g_S[r] = s;  g_D[r] = d;  g_P[r] = p;
            g_ES [r] = make_float4(__expf(s.x), __expf(s.y), __expf(s.z), __expf(s.w));
            g_ES2[r] = make_float4(__expf(NEG*s.x), __expf(NEG*s.y), __expf(NEG*s.z), __expf(NEG*s.w));
            g_ED [r] = make_float4(__expf(d.x), __expf(d.y), __expf(d.z), __expf(d.w));
            g_ED2[r] = make_float4(__expf(NEG*d.x), __expf(NEG*d.y), __expf(NEG*d.z), __expf(NEG*d.w));
        }
    }
}

// ---------------------------------------------------------------------------
// Kernel 2: main streaming kernel. Branch-free, edge-oblivious.
// Thread owns one j (ed/ed2 in registers), loops ICHUNK i-values reading a
// broadcast es/es2. exp(leaky(s+d)) = max(exp(s)exp(d), exp(.2s)exp(.2d)).
// At the write-throughput ceiling (~6.1 TB/s effective).
// ---------------------------------------------------------------------------
__global__ __launch_bounds__(256) void attn_main_kernel(float4* __restrict__ out) {
    const int j  = blockIdx.x * 256 + threadIdx.x;
    const int i0 = blockIdx.y * ICHUNK;
    const int b  = blockIdx.z;
    const int rj = b * Nn + j;

    const float4 ed  = __ldg(&g_ED [rj]);
    const float4 ed2 = __ldg(&g_ED2[rj]);

    const float4* __restrict__ esrow  = g_ES  + b * Nn + i0;
    const float4* __restrict__ es2row = g_ES2 + b * Nn + i0;
    float4* __restrict__ optr = out + ((size_t)(b * Nn + i0)) * Nn + j;

    #pragma unroll
    for (int i = 0; i < ICHUNK; i++) {
        const float4 es  = __ldg(esrow  + i);   // broadcast across warp
        const float4 es2 = __ldg(es2row + i);

        float4 e;
        e.x = fmaxf(es.x * ed.x, es2.x * ed2.x);
        e.y = fmaxf(es.y * ed.y, es2.y * ed2.y);
        e.z = fmaxf(es.z * ed.z, es2.z * ed2.z);
        e.w = fmaxf(es.w * ed.w, es2.w * ed2.w);

        const float inv = __fdividef(1.0f, (e.x + e.y) + (e.z + e.w));
        __stcs(optr + (size_t)i * Nn,
               make_float4(e.x * inv, e.y * inv, e.z * inv, e.w * inv));
    }
}

// ---------------------------------------------------------------------------
// Kernel 3: edge fixup. One thread per (edge, batch); overwrites the quad
// at (b,i,j) with the exact edge-aware value. Duplicate edges write
// identical values (multiplicity from g_cnt), so races are benign.
// ---------------------------------------------------------------------------
__global__ void fixup_kernel(const int* __restrict__ edge_index, int E,
                             float4* __restrict__ out) {
    int t = blockIdx.x * blockDim.x + threadIdx.x;
    if (t >= E * Bn) return;
    const int e = t % E;
    const int b = t / E;
    const int i = edge_index[e];
    const int j = edge_index[E + e];
    const float c = (float)g_cnt[i * Nn + j];

    const int ri = b * Nn + i, rj = b * Nn + j;
    const float4 s  = __ldg(&g_S[ri]);
    const float4 pi = __ldg(&g_P[ri]);
    const float4 d  = __ldg(&g_D[rj]);
    const float4 pj = __ldg(&g_P[rj]);

    float vx = s.x + d.x + c * (pi.x - pj.x);
    float vy = s.y + d.y + c * (pi.y - pj.y);
    float vz = s.z + d.z + c * (pi.z - pj.z);
    float vw = s.w + d.w + c * (pi.w - pj.w);
    vx = (vx > 0.0f) ? vx : NEG * vx;
    vy = (vy > 0.0f) ? vy : NEG * vy;
    vz = (vz > 0.0f) ? vz : NEG * vz;
    vw = (vw > 0.0f) ? vw : NEG * vw;

    float4 ev = make_float4(__expf(vx), __expf(vy), __expf(vz), __expf(vw));
    const float inv = __fdividef(1.0f, (ev.x + ev.y) + (ev.z + ev.w));
    out[((size_t)(b * Nn + i)) * Nn + j] =
        make_float4(ev.x * inv, ev.y * inv, ev.z * inv, ev.w * inv);
}

// ---------------------------------------------------------------------------
// Kernel 4: sparse cnt reset — zero only the entries touched by edges, so the
// NEXT launch (or replay) starts from a zero count matrix. Duplicates write
// zero twice: benign.
// ---------------------------------------------------------------------------
__global__ void reset_cnt_kernel(const int* __restrict__ edge_index, int E) {
    int e = blockIdx.x * blockDim.x + threadIdx.x;
    if (e < E) {
        int i = edge_index[e];
        int j = edge_index[E + e];
        g_cnt[i * Nn + j] = 0;
    }
}

// ---------------------------------------------------------------------------
// Launch
// Inputs (metadata order): src, edge_index, W_lin, a_src, a_dst, W_edge, a_edge
// ---------------------------------------------------------------------------
extern "C" void kernel_launch(void* const* d_in, const int* in_sizes, int n_in,
                              void* d_out, int out_size) {
    const float* src        = (const float*)d_in[0];
    const int*   edge_index = (const int*)  d_in[1];
    const float* W_lin      = (const float*)d_in[2];
    const float* a_src      = (const float*)d_in[3];
    const float* a_dst      = (const float*)d_in[4];
    const float* W_edge     = (const float*)d_in[5];
    const float* a_edge     = (const float*)d_in[6];
    const int E = in_sizes[1] / 2;

    prep_kernel<<<128, 256>>>(src, edge_index, E,
                              W_lin, a_src, a_dst, W_edge, a_edge);
    attn_main_kernel<<<dim3(Nn / 256, Nn / ICHUNK, Bn), 256>>>((float4*)d_out);
    fixup_kernel<<<(E * Bn + 255) / 256, 256>>>(edge_index, E, (float4*)d_out);
    reset_cnt_kernel<<<(E + 255) / 256, 256>>>(edge_index, E);
}

// round 7
// speedup vs baseline: 1.7158x; 1.7158x over previous
#include <cuda_runtime.h>
#include <cuda_bf16.h>
#include <cstdint>

// Problem constants (fixed shapes per reference)
#define Bn   8
#define Nn   1024
#define Fin  128
#define Cc   128
#define Ef   64
#define Hh   4
#define NEG  0.2f
#define ROWS (Bn * Nn)          // 8192
#define ICHUNK 16               // i-rows per block in main kernel

// Scratch (device globals — no allocation allowed)
__device__ float  g_M[Fin * 12];            // cols 0-3: As, 4-7: Ad, 8-11: Ae
__device__ float4 g_S [ROWS];               // s  = src @ (W_lin@a_src)
__device__ float4 g_D [ROWS];               // d  = src @ (W_lin@a_dst)
__device__ float4 g_P [ROWS];               // p  = src @ (W_edge@a_edge)
__device__ float4 g_ES [ROWS];              // exp(s)
__device__ float4 g_ES2[ROWS];              // exp(0.2 s)
__device__ float4 g_ED [ROWS];              // exp(d)
__device__ float4 g_ED2[ROWS];              // exp(0.2 d)
__device__ int    g_cnt[Nn * Nn];           // edge multiplicity matrix

// ---------------------------------------------------------------------------
// Kernel 1: fold weights (warp-per-entry, no redundancy) + dense-zero g_cnt.
// Grid: 256 blocks x 256 threads = 65536 threads = 2048 warps.
//   - every thread zeroes 4 int4 of g_cnt (4 MB total)
//   - first 1536 warps each compute one entry of M via 32-lane reduction
// ---------------------------------------------------------------------------
__global__ __launch_bounds__(256) void m_zero_kernel(
        const float* __restrict__ W_lin,
        const float* __restrict__ a_src,
        const float* __restrict__ a_dst,
        const float* __restrict__ W_edge,
        const float* __restrict__ a_edge) {
    const int t = blockIdx.x * blockDim.x + threadIdx.x;   // 0..65535

    // zero the count matrix: 262144 int4
    int4* c4 = reinterpret_cast<int4*>(g_cnt);
    #pragma unroll
    for (int k = 0; k < 4; k++)
        c4[t + k * 65536] = make_int4(0, 0, 0, 0);

    // M entries: warp gw computes M[f, col]
    const int gw   = t >> 5;
    const int lane = t & 31;
    if (gw < Fin * 12) {
        const int f   = gw / 12;
        const int col = gw % 12;
        float acc = 0.0f;
        if (col < 8) {
            const float* __restrict__ av = (col < 4) ? a_src : a_dst;
            const int h = col & 3;
            #pragma unroll
            for (int k = 0; k < 4; k++) {
                const int c = lane + k * 32;
                acc += W_lin[f * Cc + c] * av[c * Hh + h];
            }
        } else {
            const int h = col - 8;
            #pragma unroll
            for (int k = 0; k < 2; k++) {
                const int d = lane + k * 32;
                acc += W_edge[f * Ef + d] * a_edge[d * Hh + h];
            }
        }
        #pragma unroll
        for (int o = 16; o > 0; o >>= 1) acc += __shfl_xor_sync(0xffffffffu, acc, o);
        if (lane == 0) g_M[f * 12 + col] = acc;
    }
}

// ---------------------------------------------------------------------------
// Kernel 2: scatter edge multiplicities (cnt zeroed by k1) + warp-per-row
// projections & exponentials (M from k1). Phases independent; atomics issue
// early and drain under the FMA work.
// ---------------------------------------------------------------------------
__global__ __launch_bounds__(256) void rows_scatter_kernel(
        const float* __restrict__ src,
        const int*   __restrict__ edge_index, int E) {
    // ---- scatter
    {
        const int t  = blockIdx.x * blockDim.x + threadIdx.x;
        const int nt = gridDim.x * blockDim.x;
        for (int e = t; e < E; e += nt) {
            const int i = edge_index[e];
            const int j = edge_index[E + e];
            atomicAdd(&g_cnt[i * Nn + j], 1);
        }
    }

    // ---- rows
    __shared__ float sM[Fin * 12];
    for (int idx = threadIdx.x; idx < Fin * 12; idx += 256) sM[idx] = g_M[idx];
    __syncthreads();

    const int gwarp  = (blockIdx.x * blockDim.x + threadIdx.x) >> 5;
    const int lane   = threadIdx.x & 31;
    const int nwarps = (gridDim.x * blockDim.x) >> 5;

    for (int r = gwarp; r < ROWS; r += nwarps) {
        const float4 sv = reinterpret_cast<const float4*>(src + (size_t)r * Fin)[lane];
        float acc[12];
        #pragma unroll
        for (int h = 0; h < 12; h++) acc[h] = 0.0f;

        const float vals[4] = {sv.x, sv.y, sv.z, sv.w};
        #pragma unroll
        for (int k = 0; k < 4; k++) {
            const int f = lane * 4 + k;
            const float x = vals[k];
            #pragma unroll
            for (int h = 0; h < 12; h++) acc[h] += x * sM[f * 12 + h];
        }
        #pragma unroll
        for (int o = 16; o > 0; o >>= 1) {
            #pragma unroll
            for (int h = 0; h < 12; h++)
                acc[h] += __shfl_xor_sync(0xffffffffu, acc[h], o);
        }
        if (lane == 0) {
            float4 s = make_float4(acc[0], acc[1], acc[2],  acc[3]);
            float4 d = make_float4(acc[4], acc[5], acc[6],  acc[7]);
            float4 p = make_float4(acc[8], acc[9], acc[10], acc[11]);
            g_S[r] = s;  g_D[r] = d;  g_P[r] = p;
            g_ES [r] = make_float4(__expf(s.x), __expf(s.y), __expf(s.z), __expf(s.w));
            g_ES2[r] = make_float4(__expf(NEG*s.x), __expf(NEG*s.y), __expf(NEG*s.z), __expf(NEG*s.w));
            g_ED [r] = make_float4(__expf(d.x), __expf(d.y), __expf(d.z), __expf(d.w));
            g_ED2[r] = make_float4(__expf(NEG*d.x), __expf(NEG*d.y), __expf(NEG*d.z), __expf(NEG*d.w));
        }
    }
}

// ---------------------------------------------------------------------------
// Kernel 3: main streaming kernel (at the ~6.1 TB/s write ceiling).
// Thread owns one j (ed/ed2 in registers), loops ICHUNK i-values reading a
// broadcast es/es2. exp(leaky(s+d)) = max(exp(s)exp(d), exp(.2s)exp(.2d)).
// ---------------------------------------------------------------------------
__global__ __launch_bounds__(256) void attn_main_kernel(float4* __restrict__ out) {
    const int j  = blockIdx.x * 256 + threadIdx.x;
    const int i0 = blockIdx.y * ICHUNK;
    const int b  = blockIdx.z;
    const int rj = b * Nn + j;

    const float4 ed  = __ldg(&g_ED [rj]);
    const float4 ed2 = __ldg(&g_ED2[rj]);

    const float4* __restrict__ esrow  = g_ES  + b * Nn + i0;
    const float4* __restrict__ es2row = g_ES2 + b * Nn + i0;
    float4* __restrict__ optr = out + ((size_t)(b * Nn + i0)) * Nn + j;

    #pragma unroll
    for (int i = 0; i < ICHUNK; i++) {
        const float4 es  = __ldg(esrow  + i);   // broadcast across warp
        const float4 es2 = __ldg(es2row + i);

        float4 e;
        e.x = fmaxf(es.x * ed.x, es2.x * ed2.x);
        e.y = fmaxf(es.y * ed.y, es2.y * ed2.y);
        e.z = fmaxf(es.z * ed.z, es2.z * ed2.z);
        e.w = fmaxf(es.w * ed.w, es2.w * ed2.w);

        const float inv = __fdividef(1.0f, (e.x + e.y) + (e.z + e.w));
        __stcs(optr + (size_t)i * Nn,
               make_float4(e.x * inv, e.y * inv, e.z * inv, e.w * inv));
    }
}

// ---------------------------------------------------------------------------
// Kernel 4: edge fixup. ONE thread per edge handles all 8 batches (8
// independent load/compute/store groups -> high MLP, one cnt read per edge).
// Duplicate edges write identical values: benign race.
// ---------------------------------------------------------------------------
__global__ __launch_bounds__(256) void fixup_kernel(
        const int* __restrict__ edge_index, int E, float4* __restrict__ out) {
    const int e = blockIdx.x * blockDim.x + threadIdx.x;
    if (e >= E) return;
    const int i = edge_index[e];
    const int j = edge_index[E + e];
    const float c = (float)__ldg(&g_cnt[i * Nn + j]);

    #pragma unroll
    for (int b = 0; b < Bn; b++) {
        const int ri = b * Nn + i, rj = b * Nn + j;
        const float4 s  = __ldg(&g_S[ri]);
        const float4 pi = __ldg(&g_P[ri]);
        const float4 d  = __ldg(&g_D[rj]);
        const float4 pj = __ldg(&g_P[rj]);

        float vx = s.x + d.x + c * (pi.x - pj.x);
        float vy = s.y + d.y + c * (pi.y - pj.y);
        float vz = s.z + d.z + c * (pi.z - pj.z);
        float vw = s.w + d.w + c * (pi.w - pj.w);
        vx = (vx > 0.0f) ? vx : NEG * vx;
        vy = (vy > 0.0f) ? vy : NEG * vy;
        vz = (vz > 0.0f) ? vz : NEG * vz;
        vw = (vw > 0.0f) ? vw : NEG * vw;

        const float4 ev = make_float4(__expf(vx), __expf(vy), __expf(vz), __expf(vw));
        const float inv = __fdividef(1.0f, (ev.x + ev.y) + (ev.z + ev.w));
        out[(size_t)ri * Nn + j] =
            make_float4(ev.x * inv, ev.y * inv, ev.z * inv, ev.w * inv);
    }
}

// ---------------------------------------------------------------------------
// Launch
// Inputs (metadata order): src, edge_index, W_lin, a_src, a_dst, W_edge, a_edge
// ---------------------------------------------------------------------------
extern "C" void kernel_launch(void* const* d_in, const int* in_sizes, int n_in,
                              void* d_out, int out_size) {
    const float* src        = (const float*)d_in[0];
    const int*   edge_index = (const int*)  d_in[1];
    const float* W_lin      = (const float*)d_in[2];
    const float* a_src      = (const float*)d_in[3];
    const float* a_dst      = (const float*)d_in[4];
    const float* W_edge     = (const float*)d_in[5];
    const float* a_edge     = (const float*)d_in[6];
    const int E = in_sizes[1] / 2;

    m_zero_kernel<<<256, 256>>>(W_lin, a_src, a_dst, W_edge, a_edge);
    rows_scatter_kernel<<<128, 256>>>(src, edge_index, E);
    attn_main_kernel<<<dim3(Nn / 256, Nn / ICHUNK, Bn), 256>>>((float4*)d_out);
    fixup_kernel<<<(E + 255) / 256, 256>>>(edge_index, E, (float4*)d_out);
}

// round 8
// speedup vs baseline: 1.8665x; 1.0878x over previous
#include <cuda_runtime.h>
#include <cuda_bf16.h>
#include <cstdint>

// Problem constants (fixed shapes per reference)
#define Bn   8
#define Nn   1024
#define Fin  128
#define Cc   128
#define Ef   64
#define Hh   4
#define NEG  0.2f
#define ROWS (Bn * Nn)          // 8192
#define ICHUNK 16               // i-rows per block in main kernel

// Scratch (device globals — no allocation allowed)
__device__ float  g_M[Fin * 12];            // cols 0-3: As, 4-7: Ad, 8-11: Ae
__device__ float4 g_S [ROWS];               // s  = src @ (W_lin@a_src)
__device__ float4 g_D [ROWS];               // d  = src @ (W_lin@a_dst)
__device__ float4 g_P [ROWS];               // p  = src @ (W_edge@a_edge)
__device__ float4 g_ES [ROWS];              // exp(s)
__device__ float4 g_ES2[ROWS];              // exp(0.2 s)
__device__ float4 g_ED [ROWS];              // exp(d)
__device__ float4 g_ED2[ROWS];              // exp(0.2 d)
__device__ int    g_cnt[Nn * Nn];           // edge multiplicity matrix

// ---------------------------------------------------------------------------
// Kernel 1: fold weights (warp-per-entry) + dense-zero g_cnt.
// 256 blocks x 256 threads = 65536 threads = 2048 warps.
// ---------------------------------------------------------------------------
__global__ __launch_bounds__(256) void m_zero_kernel(
        const float* __restrict__ W_lin,
        const float* __restrict__ a_src,
        const float* __restrict__ a_dst,
        const float* __restrict__ W_edge,
        const float* __restrict__ a_edge) {
    const int t = blockIdx.x * blockDim.x + threadIdx.x;   // 0..65535

    // zero the count matrix: 262144 int4
    int4* c4 = reinterpret_cast<int4*>(g_cnt);
    #pragma unroll
    for (int k = 0; k < 4; k++)
        c4[t + k * 65536] = make_int4(0, 0, 0, 0);

    // M entries: warp gw computes M[f, col]
    const int gw   = t >> 5;
    const int lane = t & 31;
    if (gw < Fin * 12) {
        const int f   = gw / 12;
        const int col = gw % 12;
        float acc = 0.0f;
        if (col < 8) {
            const float* __restrict__ av = (col < 4) ? a_src : a_dst;
            const int h = col & 3;
            #pragma unroll
            for (int k = 0; k < 4; k++) {
                const int c = lane + k * 32;
                acc += W_lin[f * Cc + c] * av[c * Hh + h];
            }
        } else {
            const int h = col - 8;
            #pragma unroll
            for (int k = 0; k < 2; k++) {
                const int d = lane + k * 32;
                acc += W_edge[f * Ef + d] * a_edge[d * Hh + h];
            }
        }
        #pragma unroll
        for (int o = 16; o > 0; o >>= 1) acc += __shfl_xor_sync(0xffffffffu, acc, o);
        if (lane == 0) g_M[f * 12 + col] = acc;
    }
}

// ---------------------------------------------------------------------------
// Kernel 2: scatter edge multiplicities + warp-per-row projections & exps.
// 256 blocks: 4 rows per warp; scatter atomics drain under FMA work.
// ---------------------------------------------------------------------------
__global__ __launch_bounds__(256) void rows_scatter_kernel(
        const float* __restrict__ src,
        const int*   __restrict__ edge_index, int E) {
    // ---- scatter
    {
        const int t  = blockIdx.x * blockDim.x + threadIdx.x;
        const int nt = gridDim.x * blockDim.x;
        for (int e = t; e < E; e += nt) {
            const int i = edge_index[e];
            const int j = edge_index[E + e];
            atomicAdd(&g_cnt[i * Nn + j], 1);
        }
    }

    // ---- rows
    __shared__ float sM[Fin * 12];
    for (int idx = threadIdx.x; idx < Fin * 12; idx += 256) sM[idx] = g_M[idx];
    __syncthreads();

    const int gwarp  = (blockIdx.x * blockDim.x + threadIdx.x) >> 5;
    const int lane   = threadIdx.x & 31;
    const int nwarps = (gridDim.x * blockDim.x) >> 5;

    for (int r = gwarp; r < ROWS; r += nwarps) {
        const float4 sv = reinterpret_cast<const float4*>(src + (size_t)r * Fin)[lane];
        float acc[12];
        #pragma unroll
        for (int h = 0; h < 12; h++) acc[h] = 0.0f;

        const float vals[4] = {sv.x, sv.y, sv.z, sv.w};
        #pragma unroll
        for (int k = 0; k < 4; k++) {
            const int f = lane * 4 + k;
            const float x = vals[k];
            #pragma unroll
            for (int h = 0; h < 12; h++) acc[h] += x * sM[f * 12 + h];
        }
        #pragma unroll
        for (int o = 16; o > 0; o >>= 1) {
            #pragma unroll
            for (int h = 0; h < 12; h++)
                acc[h] += __shfl_xor_sync(0xffffffffu, acc[h], o);
        }
        if (lane == 0) {
            float4 s = make_float4(acc[0], acc[1], acc[2],  acc[3]);
            float4 d = make_float4(acc[4], acc[5], acc[6],  acc[7]);
            float4 p = make_float4(acc[8], acc[9], acc[10], acc[11]);
            g_S[r] = s;  g_D[r] = d;  g_P[r] = p;
            g_ES [r] = make_float4(__expf(s.x), __expf(s.y), __expf(s.z), __expf(s.w));
            g_ES2[r] = make_float4(__expf(NEG*s.x), __expf(NEG*s.y), __expf(NEG*s.z), __expf(NEG*s.w));
            g_ED [r] = make_float4(__expf(d.x), __expf(d.y), __expf(d.z), __expf(d.w));
            g_ED2[r] = make_float4(__expf(NEG*d.x), __expf(NEG*d.y), __expf(NEG*d.z), __expf(NEG*d.w));
        }
    }
}

// ---------------------------------------------------------------------------
// Kernel 3: main streaming kernel (at the ~6.1 TB/s write ceiling).
// Thread owns one j (ed/ed2 in registers), loops ICHUNK i-values reading a
// broadcast es/es2. exp(leaky(s+d)) = max(exp(s)exp(d), exp(.2s)exp(.2d)).
// ---------------------------------------------------------------------------
__global__ __launch_bounds__(256) void attn_main_kernel(float4* __restrict__ out) {
    const int j  = blockIdx.x * 256 + threadIdx.x;
    const int i0 = blockIdx.y * ICHUNK;
    const int b  = blockIdx.z;
    const int rj = b * Nn + j;

    const float4 ed  = __ldg(&g_ED [rj]);
    const float4 ed2 = __ldg(&g_ED2[rj]);

    const float4* __restrict__ esrow  = g_ES  + b * Nn + i0;
    const float4* __restrict__ es2row = g_ES2 + b * Nn + i0;
    float4* __restrict__ optr = out + ((size_t)(b * Nn + i0)) * Nn + j;

    #pragma unroll
    for (int i = 0; i < ICHUNK; i++) {
        const float4 es  = __ldg(esrow  + i);   // broadcast across warp
        const float4 es2 = __ldg(es2row + i);

        float4 e;
        e.x = fmaxf(es.x * ed.x, es2.x * ed2.x);
        e.y = fmaxf(es.y * ed.y, es2.y * ed2.y);
        e.z = fmaxf(es.z * ed.z, es2.z * ed2.z);
        e.w = fmaxf(es.w * ed.w, es2.w * ed2.w);

        const float inv = __fdividef(1.0f, (e.x + e.y) + (e.z + e.w));
        __stcs(optr + (size_t)i * Nn,
               make_float4(e.x * inv, e.y * inv, e.z * inv, e.w * inv));
    }
}

// ---------------------------------------------------------------------------
// Kernel 4: edge fixup. One thread per (edge, batch) -> E*Bn = 262144
// threads = 1024 blocks: full-chip occupancy, loads exposed as TLP.
// Adjacent threads share e-major grouping per batch so the cnt/index loads
// coalesce. Duplicate edges write identical values: benign race.
// ---------------------------------------------------------------------------
__global__ __launch_bounds__(256) void fixup_kernel(
        const int* __restrict__ edge_index, int E, float4* __restrict__ out) {
    const int t = blockIdx.x * blockDim.x + threadIdx.x;
    if (t >= E * Bn) return;
    const int e = t % E;          // contiguous e within a warp
    const int b = t / E;
    const int i = edge_index[e];
    const int j = edge_index[E + e];
    const float c = (float)__ldg(&g_cnt[i * Nn + j]);

    const int ri = b * Nn + i, rj = b * Nn + j;
    const float4 s  = __ldg(&g_S[ri]);
    const float4 pi = __ldg(&g_P[ri]);
    const float4 d  = __ldg(&g_D[rj]);
    const float4 pj = __ldg(&g_P[rj]);

    float vx = s.x + d.x + c * (pi.x - pj.x);
    float vy = s.y + d.y + c * (pi.y - pj.y);
    float vz = s.z + d.z + c * (pi.z - pj.z);
    float vw = s.w + d.w + c * (pi.w - pj.w);
    vx = (vx > 0.0f) ? vx : NEG * vx;
    vy = (vy > 0.0f) ? vy : NEG * vy;
    vz = (vz > 0.0f) ? vz : NEG * vz;
    vw = (vw > 0.0f) ? vw : NEG * vw;

    const float4 ev = make_float4(__expf(vx), __expf(vy), __expf(vz), __expf(vw));
    const float inv = __fdividef(1.0f, (ev.x + ev.y) + (ev.z + ev.w));
    out[(size_t)ri * Nn + j] =
        make_float4(ev.x * inv, ev.y * inv, ev.z * inv, ev.w * inv);
}

// ---------------------------------------------------------------------------
// Launch
// Inputs (metadata order): src, edge_index, W_lin, a_src, a_dst, W_edge, a_edge
// ---------------------------------------------------------------------------
extern "C" void kernel_launch(void* const* d_in, const int* in_sizes, int n_in,
                              void* d_out, int out_size) {
    const float* src        = (const float*)d_in[0];
    const int*   edge_index = (const int*)  d_in[1];
    const float* W_lin      = (const float*)d_in[2];
    const float* a_src      = (const float*)d_in[3];
    const float* a_dst      = (const float*)d_in[4];
    const float* W_edge     = (const float*)d_in[5];
    const float* a_edge     = (const float*)d_in[6];
    const int E = in_sizes[1] / 2;

    m_zero_kernel<<<256, 256>>>(W_lin, a_src, a_dst, W_edge, a_edge);
    rows_scatter_kernel<<<256, 256>>>(src, edge_index, E);
    attn_main_kernel<<<dim3(Nn / 256, Nn / ICHUNK, Bn), 256>>>((float4*)d_out);
    fixup_kernel<<<(E * Bn + 255) / 256, 256>>>(edge_index, E, (float4*)d_out);
}

// round 9
// speedup vs baseline: 1.9429x; 1.0410x over previous
#include <cuda_runtime.h>
#include <cuda_bf16.h>
#include <cstdint>

// Problem constants (fixed shapes per reference)
#define Bn   8
#define Nn   1024
#define Fin  128
#define Cc   128
#define Ef   64
#define Hh   4
#define NEG  0.2f
#define ROWS (Bn * Nn)          // 8192
#define ICHUNK 16               // i-rows per block in main kernel
#define ECHUNKS 32              // edge chunks in fixup (per batch)

// Scratch (device globals — no allocation allowed)
__device__ float  g_M[Fin * 12];            // cols 0-3: As, 4-7: Ad, 8-11: Ae
__device__ float4 g_S [ROWS];               // s  = src @ (W_lin@a_src)
__device__ float4 g_D [ROWS];               // d  = src @ (W_lin@a_dst)
__device__ float4 g_P [ROWS];               // p  = src @ (W_edge@a_edge)
__device__ float4 g_ES [ROWS];              // exp(s)
__device__ float4 g_ES2[ROWS];              // exp(0.2 s)
__device__ float4 g_ED [ROWS];              // exp(d)
__device__ float4 g_ED2[ROWS];              // exp(0.2 d)
__device__ int    g_cnt[Nn * Nn];           // edge multiplicity matrix

// ---------------------------------------------------------------------------
// Kernel 1: fold weights (warp-per-entry) + dense-zero g_cnt.
// 256 blocks x 256 threads = 65536 threads = 2048 warps.
// ---------------------------------------------------------------------------
__global__ __launch_bounds__(256) void m_zero_kernel(
        const float* __restrict__ W_lin,
        const float* __restrict__ a_src,
        const float* __restrict__ a_dst,
        const float* __restrict__ W_edge,
        const float* __restrict__ a_edge) {
    const int t = blockIdx.x * blockDim.x + threadIdx.x;   // 0..65535

    // zero the count matrix: 262144 int4
    int4* c4 = reinterpret_cast<int4*>(g_cnt);
    #pragma unroll
    for (int k = 0; k < 4; k++)
        c4[t + k * 65536] = make_int4(0, 0, 0, 0);

    // M entries: warp gw computes M[f, col]
    const int gw   = t >> 5;
    const int lane = t & 31;
    if (gw < Fin * 12) {
        const int f   = gw / 12;
        const int col = gw % 12;
        float acc = 0.0f;
        if (col < 8) {
            const float* __restrict__ av = (col < 4) ? a_src : a_dst;
            const int h = col & 3;
            #pragma unroll
            for (int k = 0; k < 4; k++) {
                const int c = lane + k * 32;
                acc += W_lin[f * Cc + c] * av[c * Hh + h];
            }
        } else {
            const int h = col - 8;
            #pragma unroll
            for (int k = 0; k < 2; k++) {
                const int d = lane + k * 32;
                acc += W_edge[f * Ef + d] * a_edge[d * Hh + h];
            }
        }
        #pragma unroll
        for (int o = 16; o > 0; o >>= 1) acc += __shfl_xor_sync(0xffffffffu, acc, o);
        if (lane == 0) g_M[f * 12 + col] = acc;
    }
}

// ---------------------------------------------------------------------------
// Kernel 2: scatter edge multiplicities + warp-per-row projections & exps.
// ---------------------------------------------------------------------------
__global__ __launch_bounds__(256) void rows_scatter_kernel(
        const float* __restrict__ src,
        const int*   __restrict__ edge_index, int E) {
    // ---- scatter
    {
        const int t  = blockIdx.x * blockDim.x + threadIdx.x;
        const int nt = gridDim.x * blockDim.x;
        for (int e = t; e < E; e += nt) {
            const int i = edge_index[e];
            const int j = edge_index[E + e];
            atomicAdd(&g_cnt[i * Nn + j], 1);
        }
    }

    // ---- rows
    __shared__ float sM[Fin * 12];
    for (int idx = threadIdx.x; idx < Fin * 12; idx += 256) sM[idx] = g_M[idx];
    __syncthreads();

    const int gwarp  = (blockIdx.x * blockDim.x + threadIdx.x) >> 5;
    const int lane   = threadIdx.x & 31;
    const int nwarps = (gridDim.x * blockDim.x) >> 5;

    for (int r = gwarp; r < ROWS; r += nwarps) {
        const float4 sv = reinterpret_cast<const float4*>(src + (size_t)r * Fin)[lane];
        float acc[12];
        #pragma unroll
        for (int h = 0; h < 12; h++) acc[h] = 0.0f;

        const float vals[4] = {sv.x, sv.y, sv.z, sv.w};
        #pragma unroll
        for (int k = 0; k < 4; k++) {
            const int f = lane * 4 + k;
            const float x = vals[k];
            #pragma unroll
            for (int h = 0; h < 12; h++) acc[h] += x * sM[f * 12 + h];
        }
        #pragma unroll
        for (int o = 16; o > 0; o >>= 1) {
            #pragma unroll
            for (int h = 0; h < 12; h++)
                acc[h] += __shfl_xor_sync(0xffffffffu, acc[h], o);
        }
        if (lane == 0) {
            float4 s = make_float4(acc[0], acc[1], acc[2],  acc[3]);
            float4 d = make_float4(acc[4], acc[5], acc[6],  acc[7]);
            float4 p = make_float4(acc[8], acc[9], acc[10], acc[11]);
            g_S[r] = s;  g_D[r] = d;  g_P[r] = p;
            g_ES [r] = make_float4(__expf(s.x), __expf(s.y), __expf(s.z), __expf(s.w));
            g_ES2[r] = make_float4(__expf(NEG*s.x), __expf(NEG*s.y), __expf(NEG*s.z), __expf(NEG*s.w));
            g_ED [r] = make_float4(__expf(d.x), __expf(d.y), __expf(d.z), __expf(d.w));
            g_ED2[r] = make_float4(__expf(NEG*d.x), __expf(NEG*d.y), __expf(NEG*d.z), __expf(NEG*d.w));
        }
    }
}

// ---------------------------------------------------------------------------
// Kernel 3: main streaming kernel (at the ~6.1 TB/s write ceiling).
// ---------------------------------------------------------------------------
__global__ __launch_bounds__(256) void attn_main_kernel(float4* __restrict__ out) {
    const int j  = blockIdx.x * 256 + threadIdx.x;
    const int i0 = blockIdx.y * ICHUNK;
    const int b  = blockIdx.z;
    const int rj = b * Nn + j;

    const float4 ed  = __ldg(&g_ED [rj]);
    const float4 ed2 = __ldg(&g_ED2[rj]);

    const float4* __restrict__ esrow  = g_ES  + b * Nn + i0;
    const float4* __restrict__ es2row = g_ES2 + b * Nn + i0;
    float4* __restrict__ optr = out + ((size_t)(b * Nn + i0)) * Nn + j;

    #pragma unroll
    for (int i = 0; i < ICHUNK; i++) {
        const float4 es  = __ldg(esrow  + i);   // broadcast across warp
        const float4 es2 = __ldg(es2row + i);

        float4 e;
        e.x = fmaxf(es.x * ed.x, es2.x * ed2.x);
        e.y = fmaxf(es.y * ed.y, es2.y * ed2.y);
        e.z = fmaxf(es.z * ed.z, es2.z * ed2.z);
        e.w = fmaxf(es.w * ed.w, es2.w * ed2.w);

        const float inv = __fdividef(1.0f, (e.x + e.y) + (e.z + e.w));
        __stcs(optr + (size_t)i * Nn,
               make_float4(e.x * inv, e.y * inv, e.z * inv, e.w * inv));
    }
}

// ---------------------------------------------------------------------------
// Kernel 4: edge fixup, smem-staged.
// Grid (ECHUNKS, Bn). Each block stages S/D/P for its batch into smem
// (48 KB, coalesced), then processes its edge chunk with all random row
// lookups hitting the smem crossbar instead of the L1tex global path.
// Duplicate edges write identical values: benign race.
// ---------------------------------------------------------------------------
__global__ __launch_bounds__(256) void fixup_kernel(
        const int* __restrict__ edge_index, int E, float4* __restrict__ out) {
    __shared__ float4 sS[Nn];    // 16 KB
    __shared__ float4 sD[Nn];    // 16 KB
    __shared__ float4 sP[Nn];    // 16 KB  (total 48 KB)

    const int b = blockIdx.y;
    const int rbase = b * Nn;

    // stage this batch's row tables (coalesced float4 loads)
    #pragma unroll
    for (int k = 0; k < Nn / 256; k++) {
        const int r = threadIdx.x + k * 256;
        sS[r] = g_S[rbase + r];
        sD[r] = g_D[rbase + r];
        sP[r] = g_P[rbase + r];
    }
    __syncthreads();

    const int per_chunk = (E + ECHUNKS - 1) / ECHUNKS;   // 1024 for E=32768
    const int e0 = blockIdx.x * per_chunk;
    const int e1 = (e0 + per_chunk < E) ? e0 + per_chunk : E;

    for (int e = e0 + threadIdx.x; e < e1; e += 256) {
        const int i = __ldg(&edge_index[e]);
        const int j = __ldg(&edge_index[E + e]);
        const float c = (float)__ldg(&g_cnt[i * Nn + j]);

        const float4 s  = sS[i];
        const float4 pi = sP[i];
        const float4 d  = sD[j];
        const float4 pj = sP[j];

        float vx = s.x + d.x + c * (pi.x - pj.x);
        float vy = s.y + d.y + c * (pi.y - pj.y);
        float vz = s.z + d.z + c * (pi.z - pj.z);
        float vw = s.w + d.w + c * (pi.w - pj.w);
        vx = (vx > 0.0f) ? vx : NEG * vx;
        vy = (vy > 0.0f) ? vy : NEG * vy;
        vz = (vz > 0.0f) ? vz : NEG * vz;
        vw = (vw > 0.0f) ? vw : NEG * vw;

        const float4 ev = make_float4(__expf(vx), __expf(vy), __expf(vz), __expf(vw));
        const float inv = __fdividef(1.0f, (ev.x + ev.y) + (ev.z + ev.w));
        out[(size_t)(rbase + i) * Nn + j] =
            make_float4(ev.x * inv, ev.y * inv, ev.z * inv, ev.w * inv);
    }
}

// ---------------------------------------------------------------------------
// Launch
// Inputs (metadata order): src, edge_index, W_lin, a_src, a_dst, W_edge, a_edge
// ---------------------------------------------------------------------------
extern "C" void kernel_launch(void* const* d_in, const int* in_sizes, int n_in,
                              void* d_out, int out_size) {
    const float* src        = (const float*)d_in[0];
    const int*   edge_index = (const int*)  d_in[1];
    const float* W_lin      = (const float*)d_in[2];
    const float* a_src      = (const float*)d_in[3];
    const float* a_dst      = (const float*)d_in[4];
    const float* W_edge     = (const float*)d_in[5];
    const float* a_edge     = (const float*)d_in[6];
    const int E = in_sizes[1] / 2;

    m_zero_kernel<<<256, 256>>>(W_lin, a_src, a_dst, W_edge, a_edge);
    rows_scatter_kernel<<<256, 256>>>(src, edge_index, E);
    attn_main_kernel<<<dim3(Nn / 256, Nn / ICHUNK, Bn), 256>>>((float4*)d_out);
    fixup_kernel<<<dim3(ECHUNKS, Bn), 256>>>(edge_index, E, (float4*)d_out);
}